// round 2
// baseline (speedup 1.0000x reference)
#include <cuda_runtime.h>

#define NN 50000
#define NE 800000

// ---------------- scratch (device globals: no allocations allowed) ----------
__device__ __align__(16) float g_ft[NN * 128];   // per-layer GEMM output
__device__ __align__(16) float g_x[NN * 128];    // layer activations
__device__ float g_e[NN];                        // per-node attention logit
__device__ float g_m[NN];                        // segment max
__device__ float g_rden[NN];                     // 1 / max(segment sum, 1e-16)
__device__ int g_rowptr[NN + 1];
__device__ int g_cnt[NN];
__device__ int g_cursor[NN];
__device__ int g_csrsrc[NE];

// ---------------- CSR build --------------------------------------------------
__global__ void k_zero() {
    int i = blockIdx.x * blockDim.x + threadIdx.x;
    if (i < NN) g_cnt[i] = 0;
}

__global__ void k_count(const int* __restrict__ dst) {
    int e = blockIdx.x * blockDim.x + threadIdx.x;
    if (e < NE) atomicAdd(&g_cnt[dst[e]], 1);
}

// single-block exclusive scan over 50000 counts (49 chunks of 1024)
__global__ void k_scan() {
    __shared__ int buf[1024];
    __shared__ int carry;
    int tid = threadIdx.x;
    if (tid == 0) carry = 0;
    __syncthreads();
    for (int base = 0; base < NN; base += 1024) {
        int i = base + tid;
        int v = (i < NN) ? g_cnt[i] : 0;
        int val = v;
        buf[tid] = val;
        __syncthreads();
        for (int off = 1; off < 1024; off <<= 1) {
            int t = (tid >= off) ? buf[tid - off] : 0;
            __syncthreads();
            val += t;
            buf[tid] = val;
            __syncthreads();
        }
        int excl = carry + val - v;
        if (i < NN) { g_rowptr[i] = excl; g_cursor[i] = excl; }
        int tot = buf[1023];
        __syncthreads();
        if (tid == 0) carry += tot;
        __syncthreads();
    }
    if (tid == 0) g_rowptr[NN] = carry;
}

__global__ void k_scatter(const int* __restrict__ src, const int* __restrict__ dst) {
    int e = blockIdx.x * blockDim.x + threadIdx.x;
    if (e < NE) {
        int d = dst[e];
        int p = atomicAdd(&g_cursor[d], 1);
        g_csrsrc[p] = src[e];
    }
}

// ---------------- GEMM: ft = X @ W, fused per-row score e_node --------------
// Packed fp32x2 FMA mainloop. Warp = (32-row subtile, 32-col group); all lanes
// of a warp read the same sW address (pure broadcast), sX is [k][row] with
// pad-stride so both store and load are conflict-free.
template <int OUTC, bool FROM_X>
__global__ void __launch_bounds__(256) k_gemm(const float* __restrict__ Xin,
                                              const float* __restrict__ W) {
    constexpr int NCG  = OUTC / 32;       // col groups (4 or 2)
    constexpr int ROWS = 256 / NCG;       // rows per block (64 or 128)
    constexpr int XSTR = ROWS + 1;        // pad stride
    __shared__ float sW[32 * OUTC];
    __shared__ float sX[32 * XSTR];
    __shared__ float ssq[ROWS * NCG];

    const float* X = FROM_X ? (const float*)g_x : Xin;

    int tid  = threadIdx.x;
    int warp = tid >> 5, lane = tid & 31;
    int cg   = warp % NCG, sub = warp / NCG;
    int rowbase = blockIdx.x * ROWS;
    int lrow = sub * 32 + lane;
    int row  = rowbase + lrow;

    unsigned long long acc[16];
#pragma unroll
    for (int j = 0; j < 16; j++) acc[j] = 0ull;

    for (int k0 = 0; k0 < 128; k0 += 32) {
        __syncthreads();
        for (int idx = tid; idx < 32 * OUTC; idx += 256) sW[idx] = W[k0 * OUTC + idx];
        {
            int kk = tid & 31, r0 = tid >> 5;
#pragma unroll
            for (int p = 0; p < ROWS / 8; p++) {
                int r = r0 + p * 8;
                int gr = rowbase + r;
                sX[kk * XSTR + r] = (gr < NN) ? X[gr * 128 + k0 + kk] : 0.f;
            }
        }
        __syncthreads();
#pragma unroll
        for (int k = 0; k < 32; k++) {
            float xv = sX[k * XSTR + lrow];
            unsigned int xu = __float_as_uint(xv);
            unsigned long long xx;
            asm("mov.b64 %0, {%1, %1};" : "=l"(xx) : "r"(xu));
            const unsigned long long* wp =
                (const unsigned long long*)&sW[k * OUTC + cg * 32];
#pragma unroll
            for (int j = 0; j < 16; j++) {
                asm("fma.rn.f32x2 %0, %1, %2, %0;"
                    : "+l"(acc[j]) : "l"(xx), "l"(wp[j]));
            }
        }
    }

    float sq = 0.f;
    if (row < NN) {
        float2* op = (float2*)&g_ft[row * OUTC + cg * 32];
#pragma unroll
        for (int j = 0; j < 16; j++) {
            float2 v = *(float2*)&acc[j];
            sq += v.x * v.x + v.y * v.y;
            op[j] = v;
        }
    }
    ssq[lrow * NCG + cg] = sq;
    __syncthreads();
    if (tid < ROWS && rowbase + tid < NN) {
        float s = 0.f;
#pragma unroll
        for (int c = 0; c < NCG; c++) s += ssq[tid * NCG + c];
        float nrm = fmaxf(sqrtf(s), 1e-8f);
        float cs  = s / (nrm * nrm);
        float val = (cs >= 0.1f) ? cs : 1e-6f;
        g_e[rowbase + tid] = logf(val);
    }
}

// ---------------- per-dst segment max + sum ---------------------------------
__global__ void k_maxden() {
    int i = blockIdx.x * blockDim.x + threadIdx.x;
    if (i >= NN) return;
    int b = g_rowptr[i], e = g_rowptr[i + 1];
    float m = -1e30f;
    for (int j = b; j < e; j++) m = fmaxf(m, g_e[g_csrsrc[j]]);
    if (b == e) m = 0.f;  // empty segment: where(isfinite(m), m, 0)
    float den = 0.f;
    for (int j = b; j < e; j++) den += __expf(g_e[g_csrsrc[j]] - m);
    g_m[i] = m;
    g_rden[i] = 1.f / fmaxf(den, 1e-16f);
}

// ---------------- aggregation: warp per dst node, fused bias(+LN+ReLU) ------
template <int OUTC, bool LN, bool TO_X>
__global__ void __launch_bounds__(256) k_agg(const float* __restrict__ bias,
                                             const float* __restrict__ lng,
                                             const float* __restrict__ lnb,
                                             float* __restrict__ OUT) {
    constexpr int VEC = OUTC / 32;  // 4 or 2 channels per lane
    int warp = threadIdx.x >> 5, lane = threadIdx.x & 31;
    int node = blockIdx.x * 8 + warp;
    if (node >= NN) return;
    int b = g_rowptr[node], e = g_rowptr[node + 1];
    float m = g_m[node], rden = g_rden[node];

    float acc[VEC];
#pragma unroll
    for (int i = 0; i < VEC; i++) acc[i] = 0.f;

    for (int j = b; j < e; j++) {
        int s = g_csrsrc[j];                       // uniform across warp
        float w = __expf(g_e[s] - m) * rden;
        if constexpr (VEC == 4) {
            float4 f = *(const float4*)&g_ft[s * OUTC + lane * 4];
            acc[0] += w * f.x; acc[1] += w * f.y;
            acc[2] += w * f.z; acc[3] += w * f.w;
        } else {
            float2 f = *(const float2*)&g_ft[s * OUTC + lane * 2];
            acc[0] += w * f.x; acc[1] += w * f.y;
        }
    }

    float v[VEC];
#pragma unroll
    for (int i = 0; i < VEC; i++) v[i] = acc[i] + bias[lane * VEC + i];

    if constexpr (LN) {
        float s = 0.f;
#pragma unroll
        for (int i = 0; i < VEC; i++) s += v[i];
#pragma unroll
        for (int off = 16; off > 0; off >>= 1) s += __shfl_xor_sync(0xffffffffu, s, off);
        float mu = s * (1.0f / OUTC);
        float vs = 0.f;
#pragma unroll
        for (int i = 0; i < VEC; i++) { float d = v[i] - mu; vs += d * d; }
#pragma unroll
        for (int off = 16; off > 0; off >>= 1) vs += __shfl_xor_sync(0xffffffffu, vs, off);
        float inv = rsqrtf(vs * (1.0f / OUTC) + 1e-5f);
        float* dstp = TO_X ? (float*)g_x : OUT;
#pragma unroll
        for (int i = 0; i < VEC; i++) {
            int c = lane * VEC + i;
            float y = (v[i] - mu) * inv * lng[c] + lnb[c];
            dstp[node * OUTC + c] = fmaxf(y, 0.f);
        }
    } else {
        float* dstp = TO_X ? (float*)g_x : OUT;
#pragma unroll
        for (int i = 0; i < VEC; i++) dstp[node * OUTC + lane * VEC + i] = v[i];
    }
}

// ---------------- launch -----------------------------------------------------
extern "C" void kernel_launch(void* const* d_in, const int* in_sizes, int n_in,
                              void* d_out, int out_size) {
    const float* feat = (const float*)d_in[0];
    const int*   src  = (const int*)d_in[1];
    const int*   dst  = (const int*)d_in[2];
    const float* W0   = (const float*)d_in[3];
    const float* b0   = (const float*)d_in[4];
    const float* W1   = (const float*)d_in[5];
    const float* b1   = (const float*)d_in[6];
    const float* W2   = (const float*)d_in[7];
    const float* b2   = (const float*)d_in[8];
    const float* ln1g = (const float*)d_in[9];
    const float* ln1b = (const float*)d_in[10];
    const float* ln2g = (const float*)d_in[11];
    const float* ln2b = (const float*)d_in[12];
    float* out = (float*)d_out;

    const int GN  = (NN + 255) / 256;   // 196
    const int GE  = (NE + 255) / 256;   // 3125
    const int GA  = (NN + 7) / 8;       // 6250

    // CSR build (graph is static but rebuilt every call: deterministic work)
    k_zero<<<GN, 256>>>();
    k_count<<<GE, 256>>>(dst);
    k_scan<<<1, 1024>>>();
    k_scatter<<<GE, 256>>>(src, dst);

    // layer 1: feat -> g_x  (conv + LN + ReLU)
    k_gemm<128, false><<<(NN + 63) / 64, 256>>>(feat, W0);
    k_maxden<<<GN, 256>>>();
    k_agg<128, true, true><<<GA, 256>>>(b0, ln1g, ln1b, nullptr);

    // layer 2: g_x -> g_x
    k_gemm<128, true><<<(NN + 63) / 64, 256>>>(nullptr, W1);
    k_maxden<<<GN, 256>>>();
    k_agg<128, true, true><<<GA, 256>>>(b1, ln2g, ln2b, nullptr);

    // layer 3: g_x -> d_out (no LN/ReLU)
    k_gemm<64, true><<<(NN + 127) / 128, 256>>>(nullptr, W2);
    k_maxden<<<GN, 256>>>();
    k_agg<64, false, false><<<GA, 256>>>(b2, nullptr, nullptr, out);
}

// round 4
// speedup vs baseline: 1.1181x; 1.1181x over previous
#include <cuda_runtime.h>

#define NN 50000
#define NE 800000

// ---------------- scratch (device globals: no allocations allowed) ----------
__device__ __align__(16) float g_ft[NN * 128];   // per-layer GEMM output
__device__ __align__(16) float g_x[NN * 128];    // layer activations
__device__ float g_p[NN];                        // exp(attention logit) = clamped cos
__device__ int g_rowptr[NN + 1];
__device__ int g_cnt[NN];
__device__ int g_cursor[NN];
__device__ int g_csrsrc[NE];

// ---------------- CSR build --------------------------------------------------
__global__ void k_zero() {
    int i = blockIdx.x * blockDim.x + threadIdx.x;
    if (i < NN) g_cnt[i] = 0;
}

__global__ void k_count(const int* __restrict__ dst) {
    int e = blockIdx.x * blockDim.x + threadIdx.x;
    if (e < NE) atomicAdd(&g_cnt[dst[e]], 1);
}

// single-block scan, shfl-based, 4 elems/thread (4096/chunk, 13 chunks)
__global__ void __launch_bounds__(1024) k_scan() {
    __shared__ int wsum[32];
    __shared__ int s_carry, s_tot;
    int tid = threadIdx.x, lane = tid & 31, warp = tid >> 5;
    if (tid == 0) s_carry = 0;
    __syncthreads();
    for (int base = 0; base < NN; base += 4096) {
        int i0 = base + tid * 4;
        int v[4];
#pragma unroll
        for (int j = 0; j < 4; j++) {
            int i = i0 + j;
            v[j] = (i < NN) ? g_cnt[i] : 0;
        }
        int t = v[0] + v[1] + v[2] + v[3];
        int inc = t;
#pragma unroll
        for (int off = 1; off < 32; off <<= 1) {
            int n = __shfl_up_sync(0xffffffffu, inc, off);
            if (lane >= off) inc += n;
        }
        if (lane == 31) wsum[warp] = inc;
        __syncthreads();
        if (warp == 0) {
            int w = wsum[lane];
            int wi = w;
#pragma unroll
            for (int off = 1; off < 32; off <<= 1) {
                int n = __shfl_up_sync(0xffffffffu, wi, off);
                if (lane >= off) wi += n;
            }
            if (lane == 31) s_tot = wi;
            wsum[lane] = wi - w;  // exclusive
        }
        __syncthreads();
        int run = s_carry + wsum[warp] + (inc - t);
#pragma unroll
        for (int j = 0; j < 4; j++) {
            int i = i0 + j;
            if (i < NN) { g_rowptr[i] = run; g_cursor[i] = run; }
            run += v[j];
        }
        __syncthreads();
        if (tid == 0) s_carry += s_tot;
        __syncthreads();
    }
    if (tid == 0) g_rowptr[NN] = s_carry;
}

__global__ void k_scatter(const int* __restrict__ src, const int* __restrict__ dst) {
    int e = blockIdx.x * blockDim.x + threadIdx.x;
    if (e < NE) {
        int d = dst[e];
        int p = atomicAdd(&g_cursor[d], 1);
        g_csrsrc[p] = src[e];
    }
}

// ---------------- GEMM: ft = X @ W, fused per-row score p_node --------------
template <int OUTC, bool FROM_X>
__global__ void __launch_bounds__(256) k_gemm(const float* __restrict__ Xin,
                                              const float* __restrict__ W) {
    constexpr int NCG  = OUTC / 32;       // col groups (4 or 2)
    constexpr int ROWS = 256 / NCG;       // rows per block (64 or 128)
    constexpr int XSTR = ROWS + 1;        // pad stride
    __shared__ float sW[32 * OUTC];
    __shared__ float sX[32 * XSTR];
    __shared__ float ssq[ROWS * NCG];

    const float* X = FROM_X ? (const float*)g_x : Xin;

    int tid  = threadIdx.x;
    int warp = tid >> 5, lane = tid & 31;
    int cg   = warp % NCG, sub = warp / NCG;
    int rowbase = blockIdx.x * ROWS;
    int lrow = sub * 32 + lane;
    int row  = rowbase + lrow;

    unsigned long long acc[16];
#pragma unroll
    for (int j = 0; j < 16; j++) acc[j] = 0ull;

    for (int k0 = 0; k0 < 128; k0 += 32) {
        __syncthreads();
        for (int idx = tid; idx < 32 * OUTC; idx += 256) sW[idx] = W[k0 * OUTC + idx];
        {
            int kk = tid & 31, r0 = tid >> 5;
#pragma unroll
            for (int p = 0; p < ROWS / 8; p++) {
                int r = r0 + p * 8;
                int gr = rowbase + r;
                sX[kk * XSTR + r] = (gr < NN) ? X[gr * 128 + k0 + kk] : 0.f;
            }
        }
        __syncthreads();
#pragma unroll
        for (int k = 0; k < 32; k++) {
            float xv = sX[k * XSTR + lrow];
            unsigned int xu = __float_as_uint(xv);
            unsigned long long xx;
            asm("mov.b64 %0, {%1, %1};" : "=l"(xx) : "r"(xu));
            const unsigned long long* wp =
                (const unsigned long long*)&sW[k * OUTC + cg * 32];
#pragma unroll
            for (int j = 0; j < 16; j++) {
                asm("fma.rn.f32x2 %0, %1, %2, %0;"
                    : "+l"(acc[j]) : "l"(xx), "l"(wp[j]));
            }
        }
    }

    float sq = 0.f;
    if (row < NN) {
        float2* op = (float2*)&g_ft[row * OUTC + cg * 32];
#pragma unroll
        for (int j = 0; j < 16; j++) {
            float2 v = *(float2*)&acc[j];
            sq += v.x * v.x + v.y * v.y;
            op[j] = v;
        }
    }
    ssq[lrow * NCG + cg] = sq;
    __syncthreads();
    if (tid < ROWS && rowbase + tid < NN) {
        float s = 0.f;
#pragma unroll
        for (int c = 0; c < NCG; c++) s += ssq[tid * NCG + c];
        float nrm = fmaxf(sqrtf(s), 1e-8f);
        float cs  = s / (nrm * nrm);
        // p = exp(e_node); softmax weights are p[src]/sum(p) (shift-invariant)
        g_p[rowbase + tid] = (cs >= 0.1f) ? cs : 1e-6f;
    }
}

// ---------------- aggregation: warp per dst node, fused softmax+bias(+LN+ReLU)
template <int OUTC, bool LN, bool TO_X>
__global__ void __launch_bounds__(256) k_agg(const float* __restrict__ bias,
                                             const float* __restrict__ lng,
                                             const float* __restrict__ lnb,
                                             float* __restrict__ OUT) {
    constexpr int VEC = OUTC / 32;  // 4 or 2 channels per lane
    int warp = threadIdx.x >> 5, lane = threadIdx.x & 31;
    int node = blockIdx.x * 8 + warp;
    if (node >= NN) return;
    int b = g_rowptr[node], e = g_rowptr[node + 1];

    // phase 1: S = sum over neighbors of p[src]  (lane-strided)
    float S = 0.f;
    for (int j = b + lane; j < e; j += 32) S += g_p[g_csrsrc[j]];
#pragma unroll
    for (int off = 16; off > 0; off >>= 1) S += __shfl_xor_sync(0xffffffffu, S, off);
    float rS = (S > 0.f) ? (1.f / S) : 0.f;

    // phase 2: weighted gather-accumulate
    float acc[VEC];
#pragma unroll
    for (int i = 0; i < VEC; i++) acc[i] = 0.f;

#pragma unroll 4
    for (int j = b; j < e; j++) {
        int s = g_csrsrc[j];                       // uniform across warp
        float w = g_p[s] * rS;
        if constexpr (VEC == 4) {
            float4 f = *(const float4*)&g_ft[s * OUTC + lane * 4];
            acc[0] += w * f.x; acc[1] += w * f.y;
            acc[2] += w * f.z; acc[3] += w * f.w;
        } else {
            float2 f = *(const float2*)&g_ft[s * OUTC + lane * 2];
            acc[0] += w * f.x; acc[1] += w * f.y;
        }
    }

    float v[VEC];
#pragma unroll
    for (int i = 0; i < VEC; i++) v[i] = acc[i] + bias[lane * VEC + i];

    if constexpr (LN) {
        float s = 0.f;
#pragma unroll
        for (int i = 0; i < VEC; i++) s += v[i];
#pragma unroll
        for (int off = 16; off > 0; off >>= 1) s += __shfl_xor_sync(0xffffffffu, s, off);
        float mu = s * (1.0f / OUTC);
        float vs = 0.f;
#pragma unroll
        for (int i = 0; i < VEC; i++) { float d = v[i] - mu; vs += d * d; }
#pragma unroll
        for (int off = 16; off > 0; off >>= 1) vs += __shfl_xor_sync(0xffffffffu, vs, off);
        float inv = rsqrtf(vs * (1.0f / OUTC) + 1e-5f);
        float* dstp = TO_X ? (float*)g_x : OUT;
#pragma unroll
        for (int i = 0; i < VEC; i++) {
            int c = lane * VEC + i;
            float y = (v[i] - mu) * inv * lng[c] + lnb[c];
            dstp[node * OUTC + c] = fmaxf(y, 0.f);
        }
    } else {
        float* dstp = TO_X ? (float*)g_x : OUT;
#pragma unroll
        for (int i = 0; i < VEC; i++) dstp[node * OUTC + lane * VEC + i] = v[i];
    }
}

// ---------------- launch -----------------------------------------------------
extern "C" void kernel_launch(void* const* d_in, const int* in_sizes, int n_in,
                              void* d_out, int out_size) {
    const float* feat = (const float*)d_in[0];
    const int*   src  = (const int*)d_in[1];
    const int*   dst  = (const int*)d_in[2];
    const float* W0   = (const float*)d_in[3];
    const float* b0   = (const float*)d_in[4];
    const float* W1   = (const float*)d_in[5];
    const float* b1   = (const float*)d_in[6];
    const float* W2   = (const float*)d_in[7];
    const float* b2   = (const float*)d_in[8];
    const float* ln1g = (const float*)d_in[9];
    const float* ln1b = (const float*)d_in[10];
    const float* ln2g = (const float*)d_in[11];
    const float* ln2b = (const float*)d_in[12];
    float* out = (float*)d_out;

    const int GN = (NN + 255) / 256;   // 196
    const int GE = (NE + 255) / 256;   // 3125
    const int GA = (NN + 7) / 8;       // 6250

    // CSR build (rebuilt every call: deterministic, no caching)
    k_zero<<<GN, 256>>>();
    k_count<<<GE, 256>>>(dst);
    k_scan<<<1, 1024>>>();
    k_scatter<<<GE, 256>>>(src, dst);

    // layer 1: feat -> g_x  (conv + LN + ReLU)
    k_gemm<128, false><<<(NN + 63) / 64, 256>>>(feat, W0);
    k_agg<128, true, true><<<GA, 256>>>(b0, ln1g, ln1b, nullptr);

    // layer 2: g_x -> g_x
    k_gemm<128, true><<<(NN + 63) / 64, 256>>>(nullptr, W1);
    k_agg<128, true, true><<<GA, 256>>>(b1, ln2g, ln2b, nullptr);

    // layer 3: g_x -> d_out (no LN/ReLU)
    k_gemm<64, true><<<(NN + 127) / 128, 256>>>(nullptr, W2);
    k_agg<64, false, false><<<GA, 256>>>(b2, nullptr, nullptr, out);
}

// round 6
// speedup vs baseline: 1.1547x; 1.0327x over previous
#include <cuda_runtime.h>

#define NN 50000
#define NE 800000

// ---------------- scratch (device globals: no allocations allowed) ----------
__device__ __align__(16) float g_ft[NN * 128];   // per-layer GEMM output
__device__ __align__(16) float g_x[NN * 128];    // layer activations
__device__ float g_p[NN];                        // exp(attention logit) = clamped cos
__device__ int g_rowptr[NN + 1];
__device__ int g_cnt[NN];                        // zero at load; re-zeroed by k_scan
__device__ int g_cursor[NN];
__device__ int g_csrsrc[NE];

// ---------------- CSR build --------------------------------------------------
__global__ void k_count(const int* __restrict__ dst) {
    int e2 = blockIdx.x * blockDim.x + threadIdx.x;
    if (e2 * 2 < NE) {
        int2 d = ((const int2*)dst)[e2];
        atomicAdd(&g_cnt[d.x], 1);
        atomicAdd(&g_cnt[d.y], 1);
    }
}

// single-block scan, shfl-based, 4 elems/thread; re-zeros g_cnt after reading
__global__ void __launch_bounds__(1024) k_scan() {
    __shared__ int wsum[32];
    __shared__ int s_carry, s_tot;
    int tid = threadIdx.x, lane = tid & 31, warp = tid >> 5;
    if (tid == 0) s_carry = 0;
    __syncthreads();
    for (int base = 0; base < NN; base += 4096) {
        int i0 = base + tid * 4;
        int v[4];
#pragma unroll
        for (int j = 0; j < 4; j++) {
            int i = i0 + j;
            v[j] = (i < NN) ? g_cnt[i] : 0;
            if (i < NN) g_cnt[i] = 0;   // restore invariant for next call
        }
        int t = v[0] + v[1] + v[2] + v[3];
        int inc = t;
#pragma unroll
        for (int off = 1; off < 32; off <<= 1) {
            int n = __shfl_up_sync(0xffffffffu, inc, off);
            if (lane >= off) inc += n;
        }
        if (lane == 31) wsum[warp] = inc;
        __syncthreads();
        if (warp == 0) {
            int w = wsum[lane];
            int wi = w;
#pragma unroll
            for (int off = 1; off < 32; off <<= 1) {
                int n = __shfl_up_sync(0xffffffffu, wi, off);
                if (lane >= off) wi += n;
            }
            if (lane == 31) s_tot = wi;
            wsum[lane] = wi - w;  // exclusive
        }
        __syncthreads();
        int run = s_carry + wsum[warp] + (inc - t);
#pragma unroll
        for (int j = 0; j < 4; j++) {
            int i = i0 + j;
            if (i < NN) { g_rowptr[i] = run; g_cursor[i] = run; }
            run += v[j];
        }
        __syncthreads();
        if (tid == 0) s_carry += s_tot;
        __syncthreads();
    }
    if (tid == 0) g_rowptr[NN] = s_carry;
}

__global__ void k_scatter(const int* __restrict__ src, const int* __restrict__ dst) {
    int e2 = blockIdx.x * blockDim.x + threadIdx.x;
    if (e2 * 2 < NE) {
        int2 d = ((const int2*)dst)[e2];
        int2 s = ((const int2*)src)[e2];
        int p0 = atomicAdd(&g_cursor[d.x], 1);
        g_csrsrc[p0] = s.x;
        int p1 = atomicAdd(&g_cursor[d.y], 1);
        g_csrsrc[p1] = s.y;
    }
}

// ---------------- GEMM: ft = X @ W, fused per-row score p_node --------------
// fp32x2 FMA mainloop; sW read via 128-bit shared loads (broadcast, no conflicts)
template <int OUTC, bool FROM_X>
__global__ void __launch_bounds__(256) k_gemm(const float* __restrict__ Xin,
                                              const float* __restrict__ W) {
    constexpr int NCG  = OUTC / 32;       // col groups (4 or 2)
    constexpr int ROWS = 256 / NCG;       // rows per block (64 or 128)
    constexpr int XSTR = ROWS + 1;        // pad stride (odd -> conflict-free)
    __shared__ __align__(16) float sW[32 * OUTC];
    __shared__ float sX[32 * XSTR];
    __shared__ float ssq[ROWS * NCG];

    const float* X = FROM_X ? (const float*)g_x : Xin;

    int tid  = threadIdx.x;
    int warp = tid >> 5, lane = tid & 31;
    int cg   = warp % NCG, sub = warp / NCG;
    int rowbase = blockIdx.x * ROWS;
    int lrow = sub * 32 + lane;
    int row  = rowbase + lrow;

    unsigned long long acc[16];
#pragma unroll
    for (int j = 0; j < 16; j++) acc[j] = 0ull;

    for (int k0 = 0; k0 < 128; k0 += 32) {
        __syncthreads();
        for (int idx = tid; idx < 32 * OUTC; idx += 256) sW[idx] = W[k0 * OUTC + idx];
        {
            int kk = tid & 31, r0 = tid >> 5;
#pragma unroll
            for (int p = 0; p < ROWS / 8; p++) {
                int r = r0 + p * 8;
                int gr = rowbase + r;
                sX[kk * XSTR + r] = (gr < NN) ? X[gr * 128 + k0 + kk] : 0.f;
            }
        }
        __syncthreads();
#pragma unroll
        for (int k = 0; k < 32; k++) {
            float xv = sX[k * XSTR + lrow];
            unsigned int xu = __float_as_uint(xv);
            unsigned long long xx;
            asm("mov.b64 %0, {%1, %1};" : "=l"(xx) : "r"(xu));
            const ulonglong2* wp = (const ulonglong2*)&sW[k * OUTC + cg * 32];
#pragma unroll
            for (int j = 0; j < 8; j++) {
                ulonglong2 u = wp[j];   // LDS.128 broadcast
                asm("fma.rn.f32x2 %0, %1, %2, %0;"
                    : "+l"(acc[2 * j]) : "l"(xx), "l"(u.x));
                asm("fma.rn.f32x2 %0, %1, %2, %0;"
                    : "+l"(acc[2 * j + 1]) : "l"(xx), "l"(u.y));
            }
        }
    }

    float sq = 0.f;
    if (row < NN) {
        float2* op = (float2*)&g_ft[row * OUTC + cg * 32];
#pragma unroll
        for (int j = 0; j < 16; j++) {
            float2 v = *(float2*)&acc[j];
            sq += v.x * v.x + v.y * v.y;
            op[j] = v;
        }
    }
    ssq[lrow * NCG + cg] = sq;
    __syncthreads();
    if (tid < ROWS && rowbase + tid < NN) {
        float s = 0.f;
#pragma unroll
        for (int c = 0; c < NCG; c++) s += ssq[tid * NCG + c];
        float nrm = fmaxf(sqrtf(s), 1e-8f);
        float cs  = s / (nrm * nrm);
        // p = exp(e_node); softmax weights are p[src]/sum(p) (shift-invariant)
        g_p[rowbase + tid] = (cs >= 0.1f) ? cs : 1e-6f;
    }
}

// ---------------- aggregation: warp per dst node, fused softmax+bias(+LN+ReLU)
template <int OUTC, bool LN, bool TO_X>
__global__ void __launch_bounds__(256) k_agg(const float* __restrict__ bias,
                                             const float* __restrict__ lng,
                                             const float* __restrict__ lnb,
                                             float* __restrict__ OUT) {
    constexpr int VEC = OUTC / 32;  // 4 or 2 channels per lane
    int warp = threadIdx.x >> 5, lane = threadIdx.x & 31;
    int node = blockIdx.x * 8 + warp;
    if (node >= NN) return;
    int b = g_rowptr[node], e = g_rowptr[node + 1];

    // phase 1: S = sum over neighbors of p[src]  (lane-strided)
    float S = 0.f;
    for (int j = b + lane; j < e; j += 32) S += g_p[g_csrsrc[j]];
#pragma unroll
    for (int off = 16; off > 0; off >>= 1) S += __shfl_xor_sync(0xffffffffu, S, off);
    float rS = (S > 0.f) ? (1.f / S) : 0.f;

    // phase 2: weighted gather-accumulate (unroll 8 -> deep MLP vs L2 latency)
    float acc[VEC];
#pragma unroll
    for (int i = 0; i < VEC; i++) acc[i] = 0.f;

#pragma unroll 8
    for (int j = b; j < e; j++) {
        int s = g_csrsrc[j];                       // uniform across warp
        float w = g_p[s] * rS;
        if constexpr (VEC == 4) {
            float4 f = *(const float4*)&g_ft[s * OUTC + lane * 4];
            acc[0] += w * f.x; acc[1] += w * f.y;
            acc[2] += w * f.z; acc[3] += w * f.w;
        } else {
            float2 f = *(const float2*)&g_ft[s * OUTC + lane * 2];
            acc[0] += w * f.x; acc[1] += w * f.y;
        }
    }

    float v[VEC];
#pragma unroll
    for (int i = 0; i < VEC; i++) v[i] = acc[i] + bias[lane * VEC + i];

    if constexpr (LN) {
        float s = 0.f;
#pragma unroll
        for (int i = 0; i < VEC; i++) s += v[i];
#pragma unroll
        for (int off = 16; off > 0; off >>= 1) s += __shfl_xor_sync(0xffffffffu, s, off);
        float mu = s * (1.0f / OUTC);
        float vs = 0.f;
#pragma unroll
        for (int i = 0; i < VEC; i++) { float d = v[i] - mu; vs += d * d; }
#pragma unroll
        for (int off = 16; off > 0; off >>= 1) vs += __shfl_xor_sync(0xffffffffu, vs, off);
        float inv = rsqrtf(vs * (1.0f / OUTC) + 1e-5f);
        float* dstp = TO_X ? (float*)g_x : OUT;
#pragma unroll
        for (int i = 0; i < VEC; i++) {
            int c = lane * VEC + i;
            float y = (v[i] - mu) * inv * lng[c] + lnb[c];
            dstp[node * OUTC + c] = fmaxf(y, 0.f);
        }
    } else {
        float* dstp = TO_X ? (float*)g_x : OUT;
#pragma unroll
        for (int i = 0; i < VEC; i++) dstp[node * OUTC + lane * VEC + i] = v[i];
    }
}

// ---------------- launch -----------------------------------------------------
extern "C" void kernel_launch(void* const* d_in, const int* in_sizes, int n_in,
                              void* d_out, int out_size) {
    const float* feat = (const float*)d_in[0];
    const int*   src  = (const int*)d_in[1];
    const int*   dst  = (const int*)d_in[2];
    const float* W0   = (const float*)d_in[3];
    const float* b0   = (const float*)d_in[4];
    const float* W1   = (const float*)d_in[5];
    const float* b1   = (const float*)d_in[6];
    const float* W2   = (const float*)d_in[7];
    const float* b2   = (const float*)d_in[8];
    const float* ln1g = (const float*)d_in[9];
    const float* ln1b = (const float*)d_in[10];
    const float* ln2g = (const float*)d_in[11];
    const float* ln2b = (const float*)d_in[12];
    float* out = (float*)d_out;

    const int GE2 = (NE / 2 + 255) / 256;  // 1563
    const int GA  = (NN + 7) / 8;          // 6250

    // CSR build (rebuilt every call; g_cnt invariant: zero at entry,
    // re-zeroed by k_scan after consumption)
    k_count<<<GE2, 256>>>(dst);
    k_scan<<<1, 1024>>>();
    k_scatter<<<GE2, 256>>>(src, dst);

    // layer 1: feat -> g_x  (conv + LN + ReLU)
    k_gemm<128, false><<<(NN + 63) / 64, 256>>>(feat, W0);
    k_agg<128, true, true><<<GA, 256>>>(b0, ln1g, ln1b, nullptr);

    // layer 2: g_x -> g_x
    k_gemm<128, true><<<(NN + 63) / 64, 256>>>(nullptr, W1);
    k_agg<128, true, true><<<GA, 256>>>(b1, ln2g, ln2b, nullptr);

    // layer 3: g_x -> d_out (no LN/ReLU)
    k_gemm<64, true><<<(NN + 127) / 128, 256>>>(nullptr, W2);
    k_agg<64, false, false><<<GA, 256>>>(b2, nullptr, nullptr, out);
}

// round 8
// speedup vs baseline: 1.1837x; 1.0252x over previous
#include <cuda_runtime.h>

#define NN 50000
#define NE 800000

// ---------------- scratch (device globals: no allocations allowed) ----------
__device__ __align__(16) float g_ft[NN * 128];   // per-layer GEMM output
__device__ __align__(16) float g_x[NN * 128];    // layer activations
__device__ float g_p[NN];                        // exp(attention logit) = clamped cos
__device__ int g_rowptr[NN + 1];
__device__ int g_cnt[NN];                        // zero at load; re-zeroed by k_scan
__device__ int g_cursor[NN];
__device__ int g_csrsrc[NE];

// ---------------- CSR build --------------------------------------------------
__global__ void k_count(const int* __restrict__ dst) {
    int e2 = blockIdx.x * blockDim.x + threadIdx.x;
    if (e2 * 2 < NE) {
        int2 d = ((const int2*)dst)[e2];
        atomicAdd(&g_cnt[d.x], 1);
        atomicAdd(&g_cnt[d.y], 1);
    }
}

// single-block scan, shfl-based, 4 elems/thread; re-zeros g_cnt after reading
__global__ void __launch_bounds__(1024) k_scan() {
    __shared__ int wsum[32];
    __shared__ int s_carry, s_tot;
    int tid = threadIdx.x, lane = tid & 31, warp = tid >> 5;
    if (tid == 0) s_carry = 0;
    __syncthreads();
    for (int base = 0; base < NN; base += 4096) {
        int i0 = base + tid * 4;
        int v[4];
#pragma unroll
        for (int j = 0; j < 4; j++) {
            int i = i0 + j;
            v[j] = (i < NN) ? g_cnt[i] : 0;
            if (i < NN) g_cnt[i] = 0;   // restore invariant for next call
        }
        int t = v[0] + v[1] + v[2] + v[3];
        int inc = t;
#pragma unroll
        for (int off = 1; off < 32; off <<= 1) {
            int n = __shfl_up_sync(0xffffffffu, inc, off);
            if (lane >= off) inc += n;
        }
        if (lane == 31) wsum[warp] = inc;
        __syncthreads();
        if (warp == 0) {
            int w = wsum[lane];
            int wi = w;
#pragma unroll
            for (int off = 1; off < 32; off <<= 1) {
                int n = __shfl_up_sync(0xffffffffu, wi, off);
                if (lane >= off) wi += n;
            }
            if (lane == 31) s_tot = wi;
            wsum[lane] = wi - w;  // exclusive
        }
        __syncthreads();
        int run = s_carry + wsum[warp] + (inc - t);
#pragma unroll
        for (int j = 0; j < 4; j++) {
            int i = i0 + j;
            if (i < NN) { g_rowptr[i] = run; g_cursor[i] = run; }
            run += v[j];
        }
        __syncthreads();
        if (tid == 0) s_carry += s_tot;
        __syncthreads();
    }
    if (tid == 0) g_rowptr[NN] = s_carry;
}

__global__ void k_scatter(const int* __restrict__ src, const int* __restrict__ dst) {
    int e2 = blockIdx.x * blockDim.x + threadIdx.x;
    if (e2 * 2 < NE) {
        int2 d = ((const int2*)dst)[e2];
        int2 s = ((const int2*)src)[e2];
        int p0 = atomicAdd(&g_cursor[d.x], 1);
        g_csrsrc[p0] = s.x;
        int p1 = atomicAdd(&g_cursor[d.y], 1);
        g_csrsrc[p1] = s.y;
    }
}

// ---------------- GEMM: ft = X @ W, fused per-row score p_node --------------
// Register-blocked: each thread computes 4 rows x 32 cols. Per k:
// 4 scalar x loads (conflict-free) + 8 broadcast LDS.128 W loads -> 64 FFMA2.
template <int OUTC, bool FROM_X>
__global__ void __launch_bounds__(128, 3) k_gemm(const float* __restrict__ Xin,
                                                 const float* __restrict__ W) {
    constexpr int NCG  = OUTC / 32;       // col groups (4 or 2)
    constexpr int ROWS = 512 / NCG;       // rows per block (128 or 256)
    constexpr int XSTR = ROWS + 1;        // odd word stride -> conflict-free
    __shared__ __align__(16) float sW[32 * OUTC];
    __shared__ float sX[32 * XSTR];
    __shared__ float ssq[ROWS * NCG];

    const float* X = FROM_X ? (const float*)g_x : Xin;

    int tid  = threadIdx.x;               // 0..127
    int warp = tid >> 5, lane = tid & 31;
    int cg   = warp % NCG;                // which 32-col group
    int half = warp / NCG;                // row half (0, or 0..1 when NCG==2)
    int rowbase = blockIdx.x * ROWS;

    __align__(16) unsigned long long acc[4][16];
#pragma unroll
    for (int r = 0; r < 4; r++)
#pragma unroll
        for (int j = 0; j < 16; j++) acc[r][j] = 0ull;

    for (int k0 = 0; k0 < 128; k0 += 32) {
        __syncthreads();
        // W tile: 32 x OUTC, vectorized copy
        {
            const float4* Wg = (const float4*)&W[k0 * OUTC];
            float4* sW4 = (float4*)sW;
#pragma unroll
            for (int i = tid; i < 8 * OUTC; i += 128) sW4[i] = Wg[i];
        }
        // X tile transposed: sX[k][row]
        {
            int kk = lane;
            for (int r = warp; r < ROWS; r += 4) {
                int gr = rowbase + r;
                sX[kk * XSTR + r] = (gr < NN) ? X[gr * 128 + k0 + kk] : 0.f;
            }
        }
        __syncthreads();
#pragma unroll 8
        for (int k = 0; k < 32; k++) {
            unsigned long long xx[4];
#pragma unroll
            for (int r = 0; r < 4; r++) {
                float xv = sX[k * XSTR + half * 128 + r * 32 + lane];
                unsigned int xu = __float_as_uint(xv);
                asm("mov.b64 %0, {%1, %1};" : "=l"(xx[r]) : "r"(xu));
            }
            const ulonglong2* wp = (const ulonglong2*)&sW[k * OUTC + cg * 32];
#pragma unroll
            for (int j = 0; j < 8; j++) {
                ulonglong2 u = wp[j];   // LDS.128 broadcast
#pragma unroll
                for (int r = 0; r < 4; r++) {
                    asm("fma.rn.f32x2 %0, %1, %2, %0;"
                        : "+l"(acc[r][2 * j]) : "l"(xx[r]), "l"(u.x));
                    asm("fma.rn.f32x2 %0, %1, %2, %0;"
                        : "+l"(acc[r][2 * j + 1]) : "l"(xx[r]), "l"(u.y));
                }
            }
        }
    }

    // epilogue: store + per-row sum-of-squares
#pragma unroll
    for (int r = 0; r < 4; r++) {
        int lrow = half * 128 + r * 32 + lane;
        int row  = rowbase + lrow;
        float sq = 0.f;
        const float* af = (const float*)acc[r];
#pragma unroll
        for (int j = 0; j < 32; j++) sq += af[j] * af[j];
        if (row < NN) {
            float4* op = (float4*)&g_ft[row * OUTC + cg * 32];
            const float4* ap = (const float4*)acc[r];
#pragma unroll
            for (int j = 0; j < 8; j++) op[j] = ap[j];
        }
        ssq[lrow * NCG + cg] = sq;
    }
    __syncthreads();
    for (int i = tid; i < ROWS; i += 128) {
        if (rowbase + i < NN) {
            float s = 0.f;
#pragma unroll
            for (int c = 0; c < NCG; c++) s += ssq[i * NCG + c];
            float nrm = fmaxf(sqrtf(s), 1e-8f);
            float cs  = s / (nrm * nrm);
            // p = exp(e_node); softmax weights are p[src]/sum(p)
            g_p[rowbase + i] = (cs >= 0.1f) ? cs : 1e-6f;
        }
    }
}

// ---------------- aggregation: warp per dst node, fused softmax+bias(+LN+ReLU)
template <int OUTC, bool LN, bool TO_X>
__global__ void __launch_bounds__(256) k_agg(const float* __restrict__ bias,
                                             const float* __restrict__ lng,
                                             const float* __restrict__ lnb,
                                             float* __restrict__ OUT) {
    constexpr int VEC = OUTC / 32;  // 4 or 2 channels per lane
    int warp = threadIdx.x >> 5, lane = threadIdx.x & 31;
    int node = blockIdx.x * 8 + warp;
    if (node >= NN) return;
    int b = g_rowptr[node], e = g_rowptr[node + 1];

    // phase 1: S = sum over neighbors of p[src]  (lane-strided)
    float S = 0.f;
    for (int j = b + lane; j < e; j += 32) S += g_p[g_csrsrc[j]];
#pragma unroll
    for (int off = 16; off > 0; off >>= 1) S += __shfl_xor_sync(0xffffffffu, S, off);
    float rS = (S > 0.f) ? (1.f / S) : 0.f;

    // phase 2: weighted gather-accumulate
    float acc[VEC];
#pragma unroll
    for (int i = 0; i < VEC; i++) acc[i] = 0.f;

#pragma unroll 8
    for (int j = b; j < e; j++) {
        int s = g_csrsrc[j];                       // uniform across warp
        float w = g_p[s] * rS;
        if constexpr (VEC == 4) {
            float4 f = *(const float4*)&g_ft[s * OUTC + lane * 4];
            acc[0] += w * f.x; acc[1] += w * f.y;
            acc[2] += w * f.z; acc[3] += w * f.w;
        } else {
            float2 f = *(const float2*)&g_ft[s * OUTC + lane * 2];
            acc[0] += w * f.x; acc[1] += w * f.y;
        }
    }

    float v[VEC];
#pragma unroll
    for (int i = 0; i < VEC; i++) v[i] = acc[i] + bias[lane * VEC + i];

    if constexpr (LN) {
        float s = 0.f;
#pragma unroll
        for (int i = 0; i < VEC; i++) s += v[i];
#pragma unroll
        for (int off = 16; off > 0; off >>= 1) s += __shfl_xor_sync(0xffffffffu, s, off);
        float mu = s * (1.0f / OUTC);
        float vs = 0.f;
#pragma unroll
        for (int i = 0; i < VEC; i++) { float d = v[i] - mu; vs += d * d; }
#pragma unroll
        for (int off = 16; off > 0; off >>= 1) vs += __shfl_xor_sync(0xffffffffu, vs, off);
        float inv = rsqrtf(vs * (1.0f / OUTC) + 1e-5f);
        float* dstp = TO_X ? (float*)g_x : OUT;
#pragma unroll
        for (int i = 0; i < VEC; i++) {
            int c = lane * VEC + i;
            float y = (v[i] - mu) * inv * lng[c] + lnb[c];
            dstp[node * OUTC + c] = fmaxf(y, 0.f);
        }
    } else {
        float* dstp = TO_X ? (float*)g_x : OUT;
#pragma unroll
        for (int i = 0; i < VEC; i++) dstp[node * OUTC + lane * VEC + i] = v[i];
    }
}

// ---------------- launch -----------------------------------------------------
extern "C" void kernel_launch(void* const* d_in, const int* in_sizes, int n_in,
                              void* d_out, int out_size) {
    const float* feat = (const float*)d_in[0];
    const int*   src  = (const int*)d_in[1];
    const int*   dst  = (const int*)d_in[2];
    const float* W0   = (const float*)d_in[3];
    const float* b0   = (const float*)d_in[4];
    const float* W1   = (const float*)d_in[5];
    const float* b1   = (const float*)d_in[6];
    const float* W2   = (const float*)d_in[7];
    const float* b2   = (const float*)d_in[8];
    const float* ln1g = (const float*)d_in[9];
    const float* ln1b = (const float*)d_in[10];
    const float* ln2g = (const float*)d_in[11];
    const float* ln2b = (const float*)d_in[12];
    float* out = (float*)d_out;

    const int GE2 = (NE / 2 + 255) / 256;  // 1563
    const int GA  = (NN + 7) / 8;          // 6250

    // CSR build (rebuilt every call; g_cnt invariant: zero at entry,
    // re-zeroed by k_scan after consumption)
    k_count<<<GE2, 256>>>(dst);
    k_scan<<<1, 1024>>>();
    k_scatter<<<GE2, 256>>>(src, dst);

    // layer 1: feat -> g_x  (conv + LN + ReLU)
    k_gemm<128, false><<<(NN + 127) / 128, 128>>>(feat, W0);
    k_agg<128, true, true><<<GA, 256>>>(b0, ln1g, ln1b, nullptr);

    // layer 2: g_x -> g_x
    k_gemm<128, true><<<(NN + 127) / 128, 128>>>(nullptr, W1);
    k_agg<128, true, true><<<GA, 256>>>(b1, ln2g, ln2b, nullptr);

    // layer 3: g_x -> d_out (no LN/ReLU)
    k_gemm<64, true><<<(NN + 255) / 256, 128>>>(nullptr, W2);
    k_agg<64, false, false><<<GA, 256>>>(b2, nullptr, nullptr, out);
}

// round 10
// speedup vs baseline: 1.2801x; 1.0814x over previous
#include <cuda_runtime.h>

#define NN 50000
#define NE 800000

// ---------------- scratch (device globals: no allocations allowed) ----------
__device__ __align__(16) float g_ft[NN * 128];   // per-layer GEMM output
__device__ __align__(16) float g_x[NN * 128];    // layer activations
__device__ float g_p[NN];                        // exp(attention logit) = clamped cos
__device__ int g_rowptr[NN + 1];
__device__ int g_cnt[NN];                        // zero at load; re-zeroed by k_scan
__device__ int g_cursor[NN];
__device__ int g_csrsrc[NE];

// ---------------- CSR build --------------------------------------------------
__global__ void k_count(const int* __restrict__ dst) {
    int e2 = blockIdx.x * blockDim.x + threadIdx.x;
    if (e2 * 2 < NE) {
        int2 d = ((const int2*)dst)[e2];
        atomicAdd(&g_cnt[d.x], 1);
        atomicAdd(&g_cnt[d.y], 1);
    }
}

// single-block scan, shfl-based, 4 elems/thread; re-zeros g_cnt after reading
__global__ void __launch_bounds__(1024) k_scan() {
    __shared__ int wsum[32];
    __shared__ int s_carry, s_tot;
    int tid = threadIdx.x, lane = tid & 31, warp = tid >> 5;
    if (tid == 0) s_carry = 0;
    __syncthreads();
    for (int base = 0; base < NN; base += 4096) {
        int i0 = base + tid * 4;
        int v[4];
#pragma unroll
        for (int j = 0; j < 4; j++) {
            int i = i0 + j;
            v[j] = (i < NN) ? g_cnt[i] : 0;
            if (i < NN) g_cnt[i] = 0;   // restore invariant for next call
        }
        int t = v[0] + v[1] + v[2] + v[3];
        int inc = t;
#pragma unroll
        for (int off = 1; off < 32; off <<= 1) {
            int n = __shfl_up_sync(0xffffffffu, inc, off);
            if (lane >= off) inc += n;
        }
        if (lane == 31) wsum[warp] = inc;
        __syncthreads();
        if (warp == 0) {
            int w = wsum[lane];
            int wi = w;
#pragma unroll
            for (int off = 1; off < 32; off <<= 1) {
                int n = __shfl_up_sync(0xffffffffu, wi, off);
                if (lane >= off) wi += n;
            }
            if (lane == 31) s_tot = wi;
            wsum[lane] = wi - w;  // exclusive
        }
        __syncthreads();
        int run = s_carry + wsum[warp] + (inc - t);
#pragma unroll
        for (int j = 0; j < 4; j++) {
            int i = i0 + j;
            if (i < NN) { g_rowptr[i] = run; g_cursor[i] = run; }
            run += v[j];
        }
        __syncthreads();
        if (tid == 0) s_carry += s_tot;
        __syncthreads();
    }
    if (tid == 0) g_rowptr[NN] = s_carry;
}

__global__ void k_scatter(const int* __restrict__ src, const int* __restrict__ dst) {
    int e2 = blockIdx.x * blockDim.x + threadIdx.x;
    if (e2 * 2 < NE) {
        int2 d = ((const int2*)dst)[e2];
        int2 s = ((const int2*)src)[e2];
        int p0 = atomicAdd(&g_cursor[d.x], 1);
        g_csrsrc[p0] = s.x;
        int p1 = atomicAdd(&g_cursor[d.y], 1);
        g_csrsrc[p1] = s.y;
    }
}

// ---------------- GEMM: ft = X @ W, fused per-row score p_node --------------
// Thread = 2 rows x 32 cols. X tile stored transposed AND pre-duplicated as
// float2 {x,x} so the f32x2 mainloop needs no packing movs:
//   per k: 2 LDS.64 (x-pairs) + 8 broadcast LDS.128 (W) + 32 FFMA2.
template <int OUTC, bool FROM_X>
__global__ void __launch_bounds__(128, 5) k_gemm(const float* __restrict__ Xin,
                                                 const float* __restrict__ W) {
    constexpr int NCG   = OUTC / 32;      // col groups (4 or 2)
    constexpr int ROWS  = 256 / NCG;      // rows per block (64 or 128)
    constexpr int XSTR2 = ROWS + 1;       // odd float2 stride -> conflict-free
    __shared__ __align__(16) float sW[32 * OUTC];
    __shared__ __align__(16) float2 sX2[32 * XSTR2];
    __shared__ float ssq[ROWS * NCG];

    const float* X = FROM_X ? (const float*)g_x : Xin;

    int tid  = threadIdx.x;               // 0..127
    int warp = tid >> 5, lane = tid & 31;
    int cg   = warp % NCG;                // which 32-col group
    int half = warp / NCG;                // row half (0 when NCG==4; 0..1 when 2)
    int rowbase = blockIdx.x * ROWS;

    __align__(16) unsigned long long acc[2][16];
#pragma unroll
    for (int r = 0; r < 2; r++)
#pragma unroll
        for (int j = 0; j < 16; j++) acc[r][j] = 0ull;

    for (int k0 = 0; k0 < 128; k0 += 32) {
        __syncthreads();
        // W tile: 32 x OUTC, vectorized copy
        {
            const float4* Wg = (const float4*)&W[k0 * OUTC];
            float4* sW4 = (float4*)sW;
#pragma unroll
            for (int i = tid; i < 8 * OUTC; i += 128) sW4[i] = Wg[i];
        }
        // X tile transposed + duplicated: sX2[k][row] = {x, x}
        {
            int kk = lane;
#pragma unroll
            for (int r = warp; r < ROWS; r += 4) {
                int gr = rowbase + r;
                float xv = (gr < NN) ? X[gr * 128 + k0 + kk] : 0.f;
                sX2[kk * XSTR2 + r] = make_float2(xv, xv);
            }
        }
        __syncthreads();
#pragma unroll 8
        for (int k = 0; k < 32; k++) {
            unsigned long long xx0 =
                *(const unsigned long long*)&sX2[k * XSTR2 + half * 64 + lane];
            unsigned long long xx1 =
                *(const unsigned long long*)&sX2[k * XSTR2 + half * 64 + 32 + lane];
            const ulonglong2* wp = (const ulonglong2*)&sW[k * OUTC + cg * 32];
#pragma unroll
            for (int j = 0; j < 8; j++) {
                ulonglong2 u = wp[j];   // LDS.128 broadcast
                asm("fma.rn.f32x2 %0, %1, %2, %0;"
                    : "+l"(acc[0][2 * j]) : "l"(xx0), "l"(u.x));
                asm("fma.rn.f32x2 %0, %1, %2, %0;"
                    : "+l"(acc[0][2 * j + 1]) : "l"(xx0), "l"(u.y));
                asm("fma.rn.f32x2 %0, %1, %2, %0;"
                    : "+l"(acc[1][2 * j]) : "l"(xx1), "l"(u.x));
                asm("fma.rn.f32x2 %0, %1, %2, %0;"
                    : "+l"(acc[1][2 * j + 1]) : "l"(xx1), "l"(u.y));
            }
        }
    }

    // epilogue: store + per-row sum-of-squares
#pragma unroll
    for (int r = 0; r < 2; r++) {
        int lrow = half * 64 + r * 32 + lane;
        int row  = rowbase + lrow;
        float sq = 0.f;
        const float* af = (const float*)acc[r];
#pragma unroll
        for (int j = 0; j < 32; j++) sq += af[j] * af[j];
        if (row < NN) {
            float4* op = (float4*)&g_ft[row * OUTC + cg * 32];
            const float4* ap = (const float4*)acc[r];
#pragma unroll
            for (int j = 0; j < 8; j++) op[j] = ap[j];
        }
        ssq[lrow * NCG + cg] = sq;
    }
    __syncthreads();
    for (int i = tid; i < ROWS; i += 128) {
        if (rowbase + i < NN) {
            float s = 0.f;
#pragma unroll
            for (int c = 0; c < NCG; c++) s += ssq[i * NCG + c];
            float nrm = fmaxf(sqrtf(s), 1e-8f);
            float cs  = s / (nrm * nrm);
            // p = exp(e_node); softmax weights are p[src]/sum(p)
            g_p[rowbase + i] = (cs >= 0.1f) ? cs : 1e-6f;
        }
    }
}

// ---------------- aggregation: warp per dst node, fused softmax+bias(+LN+ReLU)
template <int OUTC, bool LN, bool TO_X>
__global__ void __launch_bounds__(256) k_agg(const float* __restrict__ bias,
                                             const float* __restrict__ lng,
                                             const float* __restrict__ lnb,
                                             float* __restrict__ OUT) {
    constexpr int VEC = OUTC / 32;  // 4 or 2 channels per lane
    int warp = threadIdx.x >> 5, lane = threadIdx.x & 31;
    int node = blockIdx.x * 8 + warp;
    if (node >= NN) return;
    int b = g_rowptr[node], e = g_rowptr[node + 1];

    // phase 1: S = sum over neighbors of p[src]  (lane-strided)
    float S = 0.f;
    for (int j = b + lane; j < e; j += 32) S += g_p[g_csrsrc[j]];
#pragma unroll
    for (int off = 16; off > 0; off >>= 1) S += __shfl_xor_sync(0xffffffffu, S, off);
    float rS = (S > 0.f) ? (1.f / S) : 0.f;

    // phase 2: weighted gather-accumulate
    float acc[VEC];
#pragma unroll
    for (int i = 0; i < VEC; i++) acc[i] = 0.f;

#pragma unroll 8
    for (int j = b; j < e; j++) {
        int s = g_csrsrc[j];                       // uniform across warp
        float w = g_p[s] * rS;
        if constexpr (VEC == 4) {
            float4 f = *(const float4*)&g_ft[s * OUTC + lane * 4];
            acc[0] += w * f.x; acc[1] += w * f.y;
            acc[2] += w * f.z; acc[3] += w * f.w;
        } else {
            float2 f = *(const float2*)&g_ft[s * OUTC + lane * 2];
            acc[0] += w * f.x; acc[1] += w * f.y;
        }
    }

    float v[VEC];
#pragma unroll
    for (int i = 0; i < VEC; i++) v[i] = acc[i] + bias[lane * VEC + i];

    if constexpr (LN) {
        float s = 0.f;
#pragma unroll
        for (int i = 0; i < VEC; i++) s += v[i];
#pragma unroll
        for (int off = 16; off > 0; off >>= 1) s += __shfl_xor_sync(0xffffffffu, s, off);
        float mu = s * (1.0f / OUTC);
        float vs = 0.f;
#pragma unroll
        for (int i = 0; i < VEC; i++) { float d = v[i] - mu; vs += d * d; }
#pragma unroll
        for (int off = 16; off > 0; off >>= 1) vs += __shfl_xor_sync(0xffffffffu, vs, off);
        float inv = rsqrtf(vs * (1.0f / OUTC) + 1e-5f);
        float* dstp = TO_X ? (float*)g_x : OUT;
#pragma unroll
        for (int i = 0; i < VEC; i++) {
            int c = lane * VEC + i;
            float y = (v[i] - mu) * inv * lng[c] + lnb[c];
            dstp[node * OUTC + c] = fmaxf(y, 0.f);
        }
    } else {
        float* dstp = TO_X ? (float*)g_x : OUT;
#pragma unroll
        for (int i = 0; i < VEC; i++) dstp[node * OUTC + lane * VEC + i] = v[i];
    }
}

// ---------------- launch -----------------------------------------------------
extern "C" void kernel_launch(void* const* d_in, const int* in_sizes, int n_in,
                              void* d_out, int out_size) {
    const float* feat = (const float*)d_in[0];
    const int*   src  = (const int*)d_in[1];
    const int*   dst  = (const int*)d_in[2];
    const float* W0   = (const float*)d_in[3];
    const float* b0   = (const float*)d_in[4];
    const float* W1   = (const float*)d_in[5];
    const float* b1   = (const float*)d_in[6];
    const float* W2   = (const float*)d_in[7];
    const float* b2   = (const float*)d_in[8];
    const float* ln1g = (const float*)d_in[9];
    const float* ln1b = (const float*)d_in[10];
    const float* ln2g = (const float*)d_in[11];
    const float* ln2b = (const float*)d_in[12];
    float* out = (float*)d_out;

    const int GE2 = (NE / 2 + 255) / 256;  // 1563
    const int GA  = (NN + 7) / 8;          // 6250

    // CSR build (rebuilt every call; g_cnt invariant: zero at entry,
    // re-zeroed by k_scan after consumption)
    k_count<<<GE2, 256>>>(dst);
    k_scan<<<1, 1024>>>();
    k_scatter<<<GE2, 256>>>(src, dst);

    // layer 1: feat -> g_x  (conv + LN + ReLU)
    k_gemm<128, false><<<(NN + 63) / 64, 128>>>(feat, W0);
    k_agg<128, true, true><<<GA, 256>>>(b0, ln1g, ln1b, nullptr);

    // layer 2: g_x -> g_x
    k_gemm<128, true><<<(NN + 63) / 64, 128>>>(nullptr, W1);
    k_agg<128, true, true><<<GA, 256>>>(b1, ln2g, ln2b, nullptr);

    // layer 3: g_x -> d_out (no LN/ReLU)
    k_gemm<64, true><<<(NN + 127) / 128, 128>>>(nullptr, W2);
    k_agg<64, false, false><<<GA, 256>>>(b2, nullptr, nullptr, out);
}